// round 2
// baseline (speedup 1.0000x reference)
#include <cuda_runtime.h>
#include <cuda_bf16.h>
#include <math_constants.h>

// ---------------------------------------------------------------------------
// GATv2 encoder: 3 layers, N=50000 nodes, E=800000 edges.
// Strategy:
//   1) Build CSR by dst (histogram + single-block scan + scatter) each call.
//   2) Per layer: SGEMM h = A @ W + b, then one fused warp-per-node kernel
//      doing gather + leakyrelu-score + ONLINE softmax + weighted aggregation
//      (+ ELU epilogue). No atomics in the hot path, no [E,H,D] intermediates.
//   3) Final column-wise max pool -> d_out[64].
// ---------------------------------------------------------------------------

#define N_NODES 50000
#define E_EDGES 800000
#define NEG_SLOPE 0.2f

// Scratch (device globals: allocation-free per harness rules)
__device__ float g_h[N_NODES * 256];     // transformed features (pre-attention)
__device__ float g_feat[N_NODES * 256];  // layer outputs / next-layer inputs
__device__ int   g_cnt[N_NODES];
__device__ int   g_roff[N_NODES + 1];
__device__ int   g_cur[N_NODES];
__device__ int   g_srcs[E_EDGES];        // edge src ids, grouped by dst

// ---------------------------------------------------------------------------
// CSR build
// ---------------------------------------------------------------------------
__global__ void hist_kernel(const int* __restrict__ dst) {
    int e = blockIdx.x * blockDim.x + threadIdx.x;
    if (e < E_EDGES) atomicAdd(&g_cnt[dst[e]], 1);
}

__global__ void scan_kernel() {
    __shared__ int sh[1024];
    int t = threadIdx.x;
    const int per = (N_NODES + 1023) >> 10;  // 49
    int lo = t * per;
    int hi = lo + per; if (hi > N_NODES) hi = N_NODES;
    if (lo > N_NODES) lo = N_NODES;
    int sum = 0;
    for (int i = lo; i < hi; ++i) sum += g_cnt[i];
    sh[t] = sum;
    __syncthreads();
    for (int ofs = 1; ofs < 1024; ofs <<= 1) {
        int v = (t >= ofs) ? sh[t - ofs] : 0;
        __syncthreads();
        sh[t] += v;
        __syncthreads();
    }
    int run = (t == 0) ? 0 : sh[t - 1];
    for (int i = lo; i < hi; ++i) {
        g_roff[i] = run;
        g_cur[i]  = run;
        run += g_cnt[i];
    }
    if (t == 0) g_roff[N_NODES] = E_EDGES;
}

__global__ void scatter_kernel(const int* __restrict__ src, const int* __restrict__ dst) {
    int e = blockIdx.x * blockDim.x + threadIdx.x;
    if (e < E_EDGES) {
        int p = atomicAdd(&g_cur[dst[e]], 1);
        g_srcs[p] = src[e];
    }
}

// ---------------------------------------------------------------------------
// SGEMM: C[M,Ncol] = A[M,K] @ W[K,Ncol] + bias.  K%16==0, Ncol%64==0.
// BM=128, BN=64, BK=16, 256 threads, 8x4 per thread.
// ---------------------------------------------------------------------------
__global__ __launch_bounds__(256) void sgemm_kernel(
    const float* __restrict__ A, const float* __restrict__ W,
    const float* __restrict__ bias, float* __restrict__ C,
    int M, int K, int Ncol)
{
    __shared__ float As[16][128 + 4];
    __shared__ float Bs[16][64];
    const int tid = threadIdx.x;
    const int br = blockIdx.x * 128;
    const int bc = blockIdx.y * 64;
    const int ty = tid >> 4;       // 0..15
    const int tx = tid & 15;       // 0..15

    float acc[8][4];
#pragma unroll
    for (int i = 0; i < 8; ++i)
#pragma unroll
        for (int j = 0; j < 4; ++j) acc[i][j] = 0.f;

    const int a_r0 = tid >> 2;           // 0..63
    const int a_c  = (tid & 3) << 2;     // 0,4,8,12
    const int b_r  = tid >> 4;           // 0..15
    const int b_c  = (tid & 15) << 2;    // 0..60

    for (int k0 = 0; k0 < K; k0 += 16) {
#pragma unroll
        for (int rr = 0; rr < 2; ++rr) {
            int row = a_r0 + rr * 64;
            int gr  = br + row;
            float4 v = make_float4(0.f, 0.f, 0.f, 0.f);
            if (gr < M) v = *(const float4*)(A + (size_t)gr * K + k0 + a_c);
            As[a_c + 0][row] = v.x;
            As[a_c + 1][row] = v.y;
            As[a_c + 2][row] = v.z;
            As[a_c + 3][row] = v.w;
        }
        float4 wv = *(const float4*)(W + (size_t)(k0 + b_r) * Ncol + bc + b_c);
        *(float4*)&Bs[b_r][b_c] = wv;
        __syncthreads();
#pragma unroll
        for (int k = 0; k < 16; ++k) {
            float4 b4  = *(const float4*)&Bs[k][tx << 2];
            float4 alo = *(const float4*)&As[k][ty << 3];
            float4 ahi = *(const float4*)&As[k][(ty << 3) + 4];
            float av[8] = {alo.x, alo.y, alo.z, alo.w, ahi.x, ahi.y, ahi.z, ahi.w};
            float bv[4] = {b4.x, b4.y, b4.z, b4.w};
#pragma unroll
            for (int i = 0; i < 8; ++i)
#pragma unroll
                for (int j = 0; j < 4; ++j)
                    acc[i][j] = fmaf(av[i], bv[j], acc[i][j]);
        }
        __syncthreads();
    }

    float4 bb = *(const float4*)(bias + bc + (tx << 2));
    float bv[4] = {bb.x, bb.y, bb.z, bb.w};
#pragma unroll
    for (int i = 0; i < 8; ++i) {
        int gr = br + (ty << 3) + i;
        if (gr < M) {
            float4 o;
            o.x = acc[i][0] + bv[0];
            o.y = acc[i][1] + bv[1];
            o.z = acc[i][2] + bv[2];
            o.w = acc[i][3] + bv[3];
            *(float4*)(C + (size_t)gr * Ncol + bc + (tx << 2)) = o;
        }
    }
}

// ---------------------------------------------------------------------------
// Fused GAT edge kernel, H=8, D=32 (HD=256). One warp per node.
// Lane l holds float4 chunks at float offsets [4l..4l+3] (head l>>3) and
// [128+4l..128+4l+3] (head 4+(l>>3)). 3-stage xor butterfly over 8-lane
// groups yields per-head scores. Online softmax, single gather pass.
// ---------------------------------------------------------------------------
__device__ __forceinline__ float lrelu(float x) { return x > 0.f ? x : NEG_SLOPE * x; }
__device__ __forceinline__ float elu1(float x)  { return x > 0.f ? x : (__expf(x) - 1.f); }

__global__ __launch_bounds__(256) void gat_edge_h8(
    const float* __restrict__ h, const float* __restrict__ attnw,
    float* __restrict__ outp, int applyElu)
{
    int warp = (blockIdx.x * blockDim.x + threadIdx.x) >> 5;
    int lane = threadIdx.x & 31;
    if (warp >= N_NODES) return;
    const int n = warp;
    const float4* __restrict__ h4 = (const float4*)h;
    const float4* __restrict__ a4 = (const float4*)attnw;

    float4 a0 = a4[lane];
    float4 a1 = a4[32 + lane];
    float4 hd0 = h4[(size_t)n * 64 + lane];
    float4 hd1 = h4[(size_t)n * 64 + 32 + lane];

    float m0 = -CUDART_INF_F, m1 = -CUDART_INF_F;
    float s0 = 0.f, s1 = 0.f;
    float4 acc0 = make_float4(0.f, 0.f, 0.f, 0.f);
    float4 acc1 = make_float4(0.f, 0.f, 0.f, 0.f);

    int beg = g_roff[n], end = g_roff[n + 1];
    int snext = (beg < end) ? g_srcs[beg] : 0;
    for (int j = beg; j < end; ++j) {
        int s = snext;
        if (j + 1 < end) snext = g_srcs[j + 1];
        float4 hs0 = h4[(size_t)s * 64 + lane];
        float4 hs1 = h4[(size_t)s * 64 + 32 + lane];

        float p = lrelu(hs0.x + hd0.x) * a0.x;
        p = fmaf(lrelu(hs0.y + hd0.y), a0.y, p);
        p = fmaf(lrelu(hs0.z + hd0.z), a0.z, p);
        p = fmaf(lrelu(hs0.w + hd0.w), a0.w, p);
        float q = lrelu(hs1.x + hd1.x) * a1.x;
        q = fmaf(lrelu(hs1.y + hd1.y), a1.y, q);
        q = fmaf(lrelu(hs1.z + hd1.z), a1.z, q);
        q = fmaf(lrelu(hs1.w + hd1.w), a1.w, q);

        // sum over 8-lane head group
        p += __shfl_xor_sync(0xFFFFFFFFu, p, 1);
        q += __shfl_xor_sync(0xFFFFFFFFu, q, 1);
        p += __shfl_xor_sync(0xFFFFFFFFu, p, 2);
        q += __shfl_xor_sync(0xFFFFFFFFu, q, 2);
        p += __shfl_xor_sync(0xFFFFFFFFu, p, 4);
        q += __shfl_xor_sync(0xFFFFFFFFu, q, 4);

        // online softmax update, head pair (l>>3, 4+(l>>3))
        float nm = fmaxf(m0, p);
        float c  = __expf(m0 - nm);
        float e  = __expf(p - nm);
        s0 = s0 * c + e; m0 = nm;
        acc0.x = fmaf(e, hs0.x, acc0.x * c);
        acc0.y = fmaf(e, hs0.y, acc0.y * c);
        acc0.z = fmaf(e, hs0.z, acc0.z * c);
        acc0.w = fmaf(e, hs0.w, acc0.w * c);

        nm = fmaxf(m1, q);
        c  = __expf(m1 - nm);
        e  = __expf(q - nm);
        s1 = s1 * c + e; m1 = nm;
        acc1.x = fmaf(e, hs1.x, acc1.x * c);
        acc1.y = fmaf(e, hs1.y, acc1.y * c);
        acc1.z = fmaf(e, hs1.z, acc1.z * c);
        acc1.w = fmaf(e, hs1.w, acc1.w * c);
    }

    float inv0 = (s0 > 0.f) ? (1.f / s0) : 0.f;
    float inv1 = (s1 > 0.f) ? (1.f / s1) : 0.f;
    float4 o0 = make_float4(acc0.x * inv0, acc0.y * inv0, acc0.z * inv0, acc0.w * inv0);
    float4 o1 = make_float4(acc1.x * inv1, acc1.y * inv1, acc1.z * inv1, acc1.w * inv1);
    if (applyElu) {
        o0.x = elu1(o0.x); o0.y = elu1(o0.y); o0.z = elu1(o0.z); o0.w = elu1(o0.w);
        o1.x = elu1(o1.x); o1.y = elu1(o1.y); o1.z = elu1(o1.z); o1.w = elu1(o1.w);
    }
    float4* __restrict__ out4 = (float4*)outp;
    out4[(size_t)n * 64 + lane]      = o0;
    out4[(size_t)n * 64 + 32 + lane] = o1;
}

// ---------------------------------------------------------------------------
// Fused GAT edge kernel, H=1, D=64. One warp per node; lane l holds float2
// at offset 2l. Full-warp reduction for the score.
// ---------------------------------------------------------------------------
__global__ __launch_bounds__(256) void gat_edge_h1(
    const float* __restrict__ h, const float* __restrict__ attnw,
    float* __restrict__ outp)
{
    int warp = (blockIdx.x * blockDim.x + threadIdx.x) >> 5;
    int lane = threadIdx.x & 31;
    if (warp >= N_NODES) return;
    const int n = warp;
    const float2* __restrict__ h2 = (const float2*)h;
    float2 a  = ((const float2*)attnw)[lane];
    float2 hd = h2[(size_t)n * 32 + lane];

    float m = -CUDART_INF_F, ssum = 0.f;
    float2 acc = make_float2(0.f, 0.f);

    int beg = g_roff[n], end = g_roff[n + 1];
    int snext = (beg < end) ? g_srcs[beg] : 0;
    for (int j = beg; j < end; ++j) {
        int s = snext;
        if (j + 1 < end) snext = g_srcs[j + 1];
        float2 hs = h2[(size_t)s * 32 + lane];
        float p = lrelu(hs.x + hd.x) * a.x;
        p = fmaf(lrelu(hs.y + hd.y), a.y, p);
#pragma unroll
        for (int ofs = 1; ofs < 32; ofs <<= 1)
            p += __shfl_xor_sync(0xFFFFFFFFu, p, ofs);

        float nm = fmaxf(m, p);
        float c  = __expf(m - nm);
        float e  = __expf(p - nm);
        ssum = ssum * c + e; m = nm;
        acc.x = fmaf(e, hs.x, acc.x * c);
        acc.y = fmaf(e, hs.y, acc.y * c);
    }
    float inv = (ssum > 0.f) ? (1.f / ssum) : 0.f;
    float2 o = make_float2(acc.x * inv, acc.y * inv);
    ((float2*)outp)[(size_t)n * 32 + lane] = o;
}

// ---------------------------------------------------------------------------
// Max pool over nodes: out[c] = max_n f[n*64+c], c = 0..63
// ---------------------------------------------------------------------------
__global__ void maxpool_kernel(const float* __restrict__ f, float* __restrict__ out) {
    __shared__ float sh[256];
    int c = blockIdx.x;
    float mx = -CUDART_INF_F;
    for (int n = threadIdx.x; n < N_NODES; n += 256)
        mx = fmaxf(mx, f[(size_t)n * 64 + c]);
    sh[threadIdx.x] = mx;
    __syncthreads();
    for (int ofs = 128; ofs > 0; ofs >>= 1) {
        if (threadIdx.x < ofs)
            sh[threadIdx.x] = fmaxf(sh[threadIdx.x], sh[threadIdx.x + ofs]);
        __syncthreads();
    }
    if (threadIdx.x == 0) out[c] = sh[0];
}

// ---------------------------------------------------------------------------
// Launch
// ---------------------------------------------------------------------------
extern "C" void kernel_launch(void* const* d_in, const int* in_sizes, int n_in,
                              void* d_out, int out_size)
{
    const float* x   = (const float*)d_in[0];
    const int*   src = (const int*)d_in[1];
    const int*   dst = (const int*)d_in[2];
    const float* W1  = (const float*)d_in[3];
    const float* b1  = (const float*)d_in[4];
    const float* at1 = (const float*)d_in[5];
    const float* W2  = (const float*)d_in[6];
    const float* b2  = (const float*)d_in[7];
    const float* at2 = (const float*)d_in[8];
    const float* W3  = (const float*)d_in[9];
    const float* b3  = (const float*)d_in[10];
    const float* at3 = (const float*)d_in[11];
    float* out = (float*)d_out;

    float *hP = nullptr, *fP = nullptr;
    int *cntP = nullptr;
    cudaGetSymbolAddress((void**)&hP, g_h);
    cudaGetSymbolAddress((void**)&fP, g_feat);
    cudaGetSymbolAddress((void**)&cntP, g_cnt);

    // CSR build (per call; deterministic work)
    cudaMemsetAsync(cntP, 0, N_NODES * sizeof(int));
    hist_kernel<<<(E_EDGES + 255) / 256, 256>>>(dst);
    scan_kernel<<<1, 1024>>>();
    scatter_kernel<<<(E_EDGES + 255) / 256, 256>>>(src, dst);

    const int edgeGrid = N_NODES / 8;  // 8 warps/block, warp per node (50000 % 8 == 0)

    // Layer 1: x[50000,128] @ W1[128,256]
    {
        dim3 g((N_NODES + 127) / 128, 256 / 64);
        sgemm_kernel<<<g, 256>>>(x, W1, b1, hP, N_NODES, 128, 256);
        gat_edge_h8<<<edgeGrid, 256>>>(hP, at1, fP, 1);
    }
    // Layer 2: feat[50000,256] @ W2[256,256]
    {
        dim3 g((N_NODES + 127) / 128, 256 / 64);
        sgemm_kernel<<<g, 256>>>(fP, W2, b2, hP, N_NODES, 256, 256);
        gat_edge_h8<<<edgeGrid, 256>>>(hP, at2, fP, 1);
    }
    // Layer 3: feat[50000,256] @ W3[256,64]
    {
        dim3 g((N_NODES + 127) / 128, 1);
        sgemm_kernel<<<g, 256>>>(fP, W3, b3, hP, N_NODES, 256, 64);
        gat_edge_h1<<<edgeGrid, 256>>>(hP, at3, fP);
    }
    // Graph max pooling -> [64]
    maxpool_kernel<<<64, 256>>>(fP, out);
}

// round 6
// speedup vs baseline: 1.0109x; 1.0109x over previous
#include <cuda_runtime.h>
#include <cuda_bf16.h>
#include <math_constants.h>

// ---------------------------------------------------------------------------
// GATv2 encoder: 3 layers, N=50000 nodes, E=800000 edges.
//   1) CSR by dst (histogram + single-block scan + scatter).
//   2) Per layer: SGEMM h = A @ W + b (double-buffered 128x128x8), then fused
//      warp-per-node gather + leakyrelu score + ONLINE softmax + aggregation
//      (+ ELU), software-pipelined (src idx prefetch x2, row prefetch x1).
//   3) Coalesced atomic max pool -> d_out[64].
// ---------------------------------------------------------------------------

#define N_NODES 50000
#define E_EDGES 800000
#define NEG_SLOPE 0.2f

__device__ float g_h[N_NODES * 256];
__device__ float g_feat[N_NODES * 256];
__device__ int   g_cnt[N_NODES];
__device__ int   g_roff[N_NODES + 1];
__device__ int   g_cur[N_NODES];
__device__ int   g_srcs[E_EDGES];
__device__ unsigned g_pool[64];

// ---------------------------------------------------------------------------
// CSR build
// ---------------------------------------------------------------------------
__global__ void hist_kernel(const int* __restrict__ dst) {
    int e = blockIdx.x * blockDim.x + threadIdx.x;
    if (e < E_EDGES) atomicAdd(&g_cnt[dst[e]], 1);
}

__global__ void scan_kernel() {
    __shared__ int sh[1024];
    int t = threadIdx.x;
    const int per = (N_NODES + 1023) >> 10;  // 49
    int lo = t * per;
    int hi = lo + per; if (hi > N_NODES) hi = N_NODES;
    if (lo > N_NODES) lo = N_NODES;
    int sum = 0;
    for (int i = lo; i < hi; ++i) sum += g_cnt[i];
    sh[t] = sum;
    __syncthreads();
    for (int ofs = 1; ofs < 1024; ofs <<= 1) {
        int v = (t >= ofs) ? sh[t - ofs] : 0;
        __syncthreads();
        sh[t] += v;
        __syncthreads();
    }
    int run = (t == 0) ? 0 : sh[t - 1];
    for (int i = lo; i < hi; ++i) {
        g_roff[i] = run;
        g_cur[i]  = run;
        run += g_cnt[i];
    }
    if (t == 0) g_roff[N_NODES] = E_EDGES;
}

__global__ void scatter_kernel(const int* __restrict__ src, const int* __restrict__ dst) {
    int e = blockIdx.x * blockDim.x + threadIdx.x;
    if (e < E_EDGES) {
        int p = atomicAdd(&g_cur[dst[e]], 1);
        g_srcs[p] = src[e];
    }
}

// ---------------------------------------------------------------------------
// SGEMM 128x128x8, 256 threads, 8x8/thread, double-buffered smem.
// Ncol must be a multiple of 128. M-edge predicated.
// ---------------------------------------------------------------------------
__global__ __launch_bounds__(256) void sgemm128(
    const float* __restrict__ A, const float* __restrict__ W,
    const float* __restrict__ bias, float* __restrict__ C,
    int M, int K, int Ncol)
{
    __shared__ float As[2][8][128];
    __shared__ float Bs[2][8][128];
    const int tid = threadIdx.x;
    const int br = blockIdx.x * 128;
    const int bc = blockIdx.y * 128;
    const int ty = tid >> 4;            // 0..15
    const int tx = tid & 15;            // 0..15
    const int arow = tid >> 1;          // 0..127
    const int acol = (tid & 1) << 2;    // 0 or 4
    const int brow = tid >> 5;          // 0..7
    const int bcol = (tid & 31) << 2;   // 0..124

    const bool avalid = (br + arow) < M;
    const float* Aptr = A + (size_t)(br + arow) * K + acol;
    const float* Wptr = W + (size_t)brow * Ncol + bc + bcol;

    float4 aF = make_float4(0.f, 0.f, 0.f, 0.f);
    if (avalid) aF = *(const float4*)Aptr;
    float4 bF = *(const float4*)Wptr;

    As[0][acol + 0][arow] = aF.x;
    As[0][acol + 1][arow] = aF.y;
    As[0][acol + 2][arow] = aF.z;
    As[0][acol + 3][arow] = aF.w;
    *(float4*)&Bs[0][brow][bcol] = bF;
    __syncthreads();

    float acc[8][8];
#pragma unroll
    for (int i = 0; i < 8; ++i)
#pragma unroll
        for (int j = 0; j < 8; ++j) acc[i][j] = 0.f;

    const int nK = K >> 3;
    int buf = 0;
    for (int t = 0; t < nK; ++t) {
        if (t + 1 < nK) {
            if (avalid) aF = *(const float4*)(Aptr + (t + 1) * 8);
            bF = *(const float4*)(Wptr + (size_t)(t + 1) * 8 * Ncol);
        }
#pragma unroll
        for (int k = 0; k < 8; ++k) {
            float4 a0 = *(const float4*)&As[buf][k][ty << 3];
            float4 a1 = *(const float4*)&As[buf][k][(ty << 3) + 4];
            float4 b0 = *(const float4*)&Bs[buf][k][tx << 3];
            float4 b1 = *(const float4*)&Bs[buf][k][(tx << 3) + 4];
            float av[8] = {a0.x, a0.y, a0.z, a0.w, a1.x, a1.y, a1.z, a1.w};
            float bv[8] = {b0.x, b0.y, b0.z, b0.w, b1.x, b1.y, b1.z, b1.w};
#pragma unroll
            for (int i = 0; i < 8; ++i)
#pragma unroll
                for (int j = 0; j < 8; ++j)
                    acc[i][j] = fmaf(av[i], bv[j], acc[i][j]);
        }
        if (t + 1 < nK) {
            buf ^= 1;
            As[buf][acol + 0][arow] = aF.x;
            As[buf][acol + 1][arow] = aF.y;
            As[buf][acol + 2][arow] = aF.z;
            As[buf][acol + 3][arow] = aF.w;
            *(float4*)&Bs[buf][brow][bcol] = bF;
            __syncthreads();
        }
    }

    float4 bb0 = *(const float4*)(bias + bc + (tx << 3));
    float4 bb1 = *(const float4*)(bias + bc + (tx << 3) + 4);
    float bv[8] = {bb0.x, bb0.y, bb0.z, bb0.w, bb1.x, bb1.y, bb1.z, bb1.w};
#pragma unroll
    for (int i = 0; i < 8; ++i) {
        int gr = br + (ty << 3) + i;
        if (gr < M) {
            float4 o0, o1;
            o0.x = acc[i][0] + bv[0]; o0.y = acc[i][1] + bv[1];
            o0.z = acc[i][2] + bv[2]; o0.w = acc[i][3] + bv[3];
            o1.x = acc[i][4] + bv[4]; o1.y = acc[i][5] + bv[5];
            o1.z = acc[i][6] + bv[6]; o1.w = acc[i][7] + bv[7];
            *(float4*)(C + (size_t)gr * Ncol + bc + (tx << 3)) = o0;
            *(float4*)(C + (size_t)gr * Ncol + bc + (tx << 3) + 4) = o1;
        }
    }
}

// ---------------------------------------------------------------------------
// SGEMM 128x64x16 (for Ncol=64, layer 3)
// ---------------------------------------------------------------------------
__global__ __launch_bounds__(256) void sgemm_kernel(
    const float* __restrict__ A, const float* __restrict__ W,
    const float* __restrict__ bias, float* __restrict__ C,
    int M, int K, int Ncol)
{
    __shared__ float As[16][128 + 4];
    __shared__ float Bs[16][64];
    const int tid = threadIdx.x;
    const int br = blockIdx.x * 128;
    const int bc = blockIdx.y * 64;
    const int ty = tid >> 4;
    const int tx = tid & 15;

    float acc[8][4];
#pragma unroll
    for (int i = 0; i < 8; ++i)
#pragma unroll
        for (int j = 0; j < 4; ++j) acc[i][j] = 0.f;

    const int a_r0 = tid >> 2;
    const int a_c  = (tid & 3) << 2;
    const int b_r  = tid >> 4;
    const int b_c  = (tid & 15) << 2;

    for (int k0 = 0; k0 < K; k0 += 16) {
#pragma unroll
        for (int rr = 0; rr < 2; ++rr) {
            int row = a_r0 + rr * 64;
            int gr  = br + row;
            float4 v = make_float4(0.f, 0.f, 0.f, 0.f);
            if (gr < M) v = *(const float4*)(A + (size_t)gr * K + k0 + a_c);
            As[a_c + 0][row] = v.x;
            As[a_c + 1][row] = v.y;
            As[a_c + 2][row] = v.z;
            As[a_c + 3][row] = v.w;
        }
        float4 wv = *(const float4*)(W + (size_t)(k0 + b_r) * Ncol + bc + b_c);
        *(float4*)&Bs[b_r][b_c] = wv;
        __syncthreads();
#pragma unroll
        for (int k = 0; k < 16; ++k) {
            float4 b4  = *(const float4*)&Bs[k][tx << 2];
            float4 alo = *(const float4*)&As[k][ty << 3];
            float4 ahi = *(const float4*)&As[k][(ty << 3) + 4];
            float av[8] = {alo.x, alo.y, alo.z, alo.w, ahi.x, ahi.y, ahi.z, ahi.w};
            float bv[4] = {b4.x, b4.y, b4.z, b4.w};
#pragma unroll
            for (int i = 0; i < 8; ++i)
#pragma unroll
                for (int j = 0; j < 4; ++j)
                    acc[i][j] = fmaf(av[i], bv[j], acc[i][j]);
        }
        __syncthreads();
    }

    float4 bb = *(const float4*)(bias + bc + (tx << 2));
    float bv[4] = {bb.x, bb.y, bb.z, bb.w};
#pragma unroll
    for (int i = 0; i < 8; ++i) {
        int gr = br + (ty << 3) + i;
        if (gr < M) {
            float4 o;
            o.x = acc[i][0] + bv[0];
            o.y = acc[i][1] + bv[1];
            o.z = acc[i][2] + bv[2];
            o.w = acc[i][3] + bv[3];
            *(float4*)(C + (size_t)gr * Ncol + bc + (tx << 2)) = o;
        }
    }
}

// ---------------------------------------------------------------------------
// Fused GAT edge kernels (online softmax, software-pipelined gathers)
// ---------------------------------------------------------------------------
__device__ __forceinline__ float lrelu(float x) { return x > 0.f ? x : NEG_SLOPE * x; }
__device__ __forceinline__ float elu1(float x)  { return x > 0.f ? x : (__expf(x) - 1.f); }

__global__ __launch_bounds__(256) void gat_edge_h8(
    const float* __restrict__ h, const float* __restrict__ attnw,
    float* __restrict__ outp, int applyElu)
{
    int warp = (blockIdx.x * blockDim.x + threadIdx.x) >> 5;
    int lane = threadIdx.x & 31;
    if (warp >= N_NODES) return;
    const int n = warp;
    const float4* __restrict__ h4 = (const float4*)h;
    const float4* __restrict__ a4 = (const float4*)attnw;

    float4 a0 = a4[lane];
    float4 a1 = a4[32 + lane];
    float4 hd0 = h4[(size_t)n * 64 + lane];
    float4 hd1 = h4[(size_t)n * 64 + 32 + lane];

    float m0 = -CUDART_INF_F, m1 = -CUDART_INF_F;
    float s0 = 0.f, s1 = 0.f;
    float4 acc0 = make_float4(0.f, 0.f, 0.f, 0.f);
    float4 acc1 = make_float4(0.f, 0.f, 0.f, 0.f);

    const int beg = g_roff[n], end = g_roff[n + 1];
    // pipeline: src index prefetched 2 ahead, feature rows 1 ahead
    int s_cur  = (beg < end)     ? g_srcs[beg]     : 0;
    int s_next = (beg + 1 < end) ? g_srcs[beg + 1] : 0;
    float4 cs0 = h4[(size_t)s_cur * 64 + lane];
    float4 cs1 = h4[(size_t)s_cur * 64 + 32 + lane];

    for (int j = beg; j < end; ++j) {
        // issue next row gather before the dependent chain
        float4 ns0 = h4[(size_t)s_next * 64 + lane];
        float4 ns1 = h4[(size_t)s_next * 64 + 32 + lane];
        int s_nn = (j + 2 < end) ? g_srcs[j + 2] : 0;

        float p = lrelu(cs0.x + hd0.x) * a0.x;
        p = fmaf(lrelu(cs0.y + hd0.y), a0.y, p);
        p = fmaf(lrelu(cs0.z + hd0.z), a0.z, p);
        p = fmaf(lrelu(cs0.w + hd0.w), a0.w, p);
        float q = lrelu(cs1.x + hd1.x) * a1.x;
        q = fmaf(lrelu(cs1.y + hd1.y), a1.y, q);
        q = fmaf(lrelu(cs1.z + hd1.z), a1.z, q);
        q = fmaf(lrelu(cs1.w + hd1.w), a1.w, q);

        p += __shfl_xor_sync(0xFFFFFFFFu, p, 1);
        q += __shfl_xor_sync(0xFFFFFFFFu, q, 1);
        p += __shfl_xor_sync(0xFFFFFFFFu, p, 2);
        q += __shfl_xor_sync(0xFFFFFFFFu, q, 2);
        p += __shfl_xor_sync(0xFFFFFFFFu, p, 4);
        q += __shfl_xor_sync(0xFFFFFFFFu, q, 4);

        float nm = fmaxf(m0, p);
        float c  = __expf(m0 - nm);
        float e  = __expf(p - nm);
        s0 = s0 * c + e; m0 = nm;
        acc0.x = fmaf(e, cs0.x, acc0.x * c);
        acc0.y = fmaf(e, cs0.y, acc0.y * c);
        acc0.z = fmaf(e, cs0.z, acc0.z * c);
        acc0.w = fmaf(e, cs0.w, acc0.w * c);

        nm = fmaxf(m1, q);
        c  = __expf(m1 - nm);
        e  = __expf(q - nm);
        s1 = s1 * c + e; m1 = nm;
        acc1.x = fmaf(e, cs1.x, acc1.x * c);
        acc1.y = fmaf(e, cs1.y, acc1.y * c);
        acc1.z = fmaf(e, cs1.z, acc1.z * c);
        acc1.w = fmaf(e, cs1.w, acc1.w * c);

        cs0 = ns0; cs1 = ns1;
        s_next = s_nn;
    }

    float inv0 = (s0 > 0.f) ? (1.f / s0) : 0.f;
    float inv1 = (s1 > 0.f) ? (1.f / s1) : 0.f;
    float4 o0 = make_float4(acc0.x * inv0, acc0.y * inv0, acc0.z * inv0, acc0.w * inv0);
    float4 o1 = make_float4(acc1.x * inv1, acc1.y * inv1, acc1.z * inv1, acc1.w * inv1);
    if (applyElu) {
        o0.x = elu1(o0.x); o0.y = elu1(o0.y); o0.z = elu1(o0.z); o0.w = elu1(o0.w);
        o1.x = elu1(o1.x); o1.y = elu1(o1.y); o1.z = elu1(o1.z); o1.w = elu1(o1.w);
    }
    float4* __restrict__ out4 = (float4*)outp;
    out4[(size_t)n * 64 + lane]      = o0;
    out4[(size_t)n * 64 + 32 + lane] = o1;
}

__global__ __launch_bounds__(256) void gat_edge_h1(
    const float* __restrict__ h, const float* __restrict__ attnw,
    float* __restrict__ outp)
{
    int warp = (blockIdx.x * blockDim.x + threadIdx.x) >> 5;
    int lane = threadIdx.x & 31;
    if (warp >= N_NODES) return;
    const int n = warp;
    const float2* __restrict__ h2 = (const float2*)h;
    float2 a  = ((const float2*)attnw)[lane];
    float2 hd = h2[(size_t)n * 32 + lane];

    float m = -CUDART_INF_F, ssum = 0.f;
    float2 acc = make_float2(0.f, 0.f);

    const int beg = g_roff[n], end = g_roff[n + 1];
    int s_cur  = (beg < end)     ? g_srcs[beg]     : 0;
    int s_next = (beg + 1 < end) ? g_srcs[beg + 1] : 0;
    float2 cs = h2[(size_t)s_cur * 32 + lane];

    for (int j = beg; j < end; ++j) {
        float2 ns = h2[(size_t)s_next * 32 + lane];
        int s_nn = (j + 2 < end) ? g_srcs[j + 2] : 0;

        float p = lrelu(cs.x + hd.x) * a.x;
        p = fmaf(lrelu(cs.y + hd.y), a.y, p);
#pragma unroll
        for (int ofs = 1; ofs < 32; ofs <<= 1)
            p += __shfl_xor_sync(0xFFFFFFFFu, p, ofs);

        float nm = fmaxf(m, p);
        float c  = __expf(m - nm);
        float e  = __expf(p - nm);
        ssum = ssum * c + e; m = nm;
        acc.x = fmaf(e, cs.x, acc.x * c);
        acc.y = fmaf(e, cs.y, acc.y * c);

        cs = ns;
        s_next = s_nn;
    }
    float inv = (ssum > 0.f) ? (1.f / ssum) : 0.f;
    ((float2*)outp)[(size_t)n * 32 + lane] = make_float2(acc.x * inv, acc.y * inv);
}

// ---------------------------------------------------------------------------
// Coalesced max pool: f is [N,64]; block reads full rows (float4), reduces to
// 16 float4 column maxes in smem, atomicMax (monotone uint map) into g_pool.
// ---------------------------------------------------------------------------
__device__ __forceinline__ unsigned fmap(float f) {
    unsigned u = __float_as_uint(f);
    return (u & 0x80000000u) ? ~u : (u | 0x80000000u);
}

__global__ __launch_bounds__(256) void maxpool_kernel(const float* __restrict__ f) {
    __shared__ float4 sh[256];
    const float4* __restrict__ f4 = (const float4*)f;
    int cg = threadIdx.x & 15;        // float4 column group 0..15
    int rr = threadIdx.x >> 4;        // 0..15
    float4 mx = make_float4(-CUDART_INF_F, -CUDART_INF_F, -CUDART_INF_F, -CUDART_INF_F);
    for (int n = blockIdx.x * 16 + rr; n < N_NODES; n += gridDim.x * 16) {
        float4 v = f4[(size_t)n * 16 + cg];
        mx.x = fmaxf(mx.x, v.x); mx.y = fmaxf(mx.y, v.y);
        mx.z = fmaxf(mx.z, v.z); mx.w = fmaxf(mx.w, v.w);
    }
    sh[threadIdx.x] = mx;
    __syncthreads();
    for (int ofs = 128; ofs >= 16; ofs >>= 1) {
        if (threadIdx.x < ofs) {
            float4 o = sh[threadIdx.x + ofs];
            float4 m2 = sh[threadIdx.x];
            m2.x = fmaxf(m2.x, o.x); m2.y = fmaxf(m2.y, o.y);
            m2.z = fmaxf(m2.z, o.z); m2.w = fmaxf(m2.w, o.w);
            sh[threadIdx.x] = m2;
        }
        __syncthreads();
    }
    if (threadIdx.x < 16) {
        float4 m2 = sh[threadIdx.x];
        atomicMax(&g_pool[threadIdx.x * 4 + 0], fmap(m2.x));
        atomicMax(&g_pool[threadIdx.x * 4 + 1], fmap(m2.y));
        atomicMax(&g_pool[threadIdx.x * 4 + 2], fmap(m2.z));
        atomicMax(&g_pool[threadIdx.x * 4 + 3], fmap(m2.w));
    }
}

__global__ void pool_final(float* __restrict__ out) {
    int c = threadIdx.x;
    if (c < 64) {
        unsigned v = g_pool[c];
        out[c] = (v & 0x80000000u) ? __uint_as_float(v ^ 0x80000000u)
                                   : __uint_as_float(~v);
    }
}

// ---------------------------------------------------------------------------
// Launch
// ---------------------------------------------------------------------------
extern "C" void kernel_launch(void* const* d_in, const int* in_sizes, int n_in,
                              void* d_out, int out_size)
{
    const float* x   = (const float*)d_in[0];
    const int*   src = (const int*)d_in[1];
    const int*   dst = (const int*)d_in[2];
    const float* W1  = (const float*)d_in[3];
    const float* b1  = (const float*)d_in[4];
    const float* at1 = (const float*)d_in[5];
    const float* W2  = (const float*)d_in[6];
    const float* b2  = (const float*)d_in[7];
    const float* at2 = (const float*)d_in[8];
    const float* W3  = (const float*)d_in[9];
    const float* b3  = (const float*)d_in[10];
    const float* at3 = (const float*)d_in[11];
    float* out = (float*)d_out;

    float *hP = nullptr, *fP = nullptr;
    int *cntP = nullptr;
    unsigned* poolP = nullptr;
    cudaGetSymbolAddress((void**)&hP, g_h);
    cudaGetSymbolAddress((void**)&fP, g_feat);
    cudaGetSymbolAddress((void**)&cntP, g_cnt);
    cudaGetSymbolAddress((void**)&poolP, g_pool);

    cudaMemsetAsync(cntP, 0, N_NODES * sizeof(int));
    cudaMemsetAsync(poolP, 0, 64 * sizeof(unsigned));
    hist_kernel<<<(E_EDGES + 255) / 256, 256>>>(dst);
    scan_kernel<<<1, 1024>>>();
    scatter_kernel<<<(E_EDGES + 255) / 256, 256>>>(src, dst);

    const int edgeGrid = N_NODES / 8;  // 8 warps/block

    // Layer 1: x[50000,128] @ W1[128,256]
    {
        dim3 g((N_NODES + 127) / 128, 256 / 128);
        sgemm128<<<g, 256>>>(x, W1, b1, hP, N_NODES, 128, 256);
        gat_edge_h8<<<edgeGrid, 256>>>(hP, at1, fP, 1);
    }
    // Layer 2: feat[50000,256] @ W2[256,256]
    {
        dim3 g((N_NODES + 127) / 128, 256 / 128);
        sgemm128<<<g, 256>>>(fP, W2, b2, hP, N_NODES, 256, 256);
        gat_edge_h8<<<edgeGrid, 256>>>(hP, at2, fP, 1);
    }
    // Layer 3: feat[50000,256] @ W3[256,64]
    {
        dim3 g((N_NODES + 127) / 128, 1);
        sgemm_kernel<<<g, 256>>>(fP, W3, b3, hP, N_NODES, 256, 64);
        gat_edge_h1<<<edgeGrid, 256>>>(hP, at3, fP);
    }
    maxpool_kernel<<<196, 256>>>(fP);
    pool_final<<<1, 64>>>(out);
}

// round 7
// speedup vs baseline: 1.0837x; 1.0720x over previous
#include <cuda_runtime.h>
#include <cuda_bf16.h>
#include <math_constants.h>

// ---------------------------------------------------------------------------
// GATv2 encoder: 3 layers, N=50000 nodes, E=800000 edges.
//   1) CSR by dst (histogram + single-block scan + scatter).
//   2) Per layer: SGEMM (128x64x16, register-staged prefetch), then fused
//      warp-per-node PAIR-UNROLLED gather + leakyrelu score + merged online
//      softmax + aggregation (+ ELU).
//   3) Coalesced atomic max pool -> d_out[64].
// ---------------------------------------------------------------------------

#define N_NODES 50000
#define E_EDGES 800000
#define NEG_SLOPE 0.2f

__device__ float g_h[N_NODES * 256];
__device__ float g_feat[N_NODES * 256];
__device__ int   g_cnt[N_NODES];
__device__ int   g_roff[N_NODES + 1];
__device__ int   g_cur[N_NODES];
__device__ int   g_srcs[E_EDGES];
__device__ unsigned g_pool[64];

// ---------------------------------------------------------------------------
// CSR build
// ---------------------------------------------------------------------------
__global__ void hist_kernel(const int* __restrict__ dst) {
    int e = blockIdx.x * blockDim.x + threadIdx.x;
    if (e < E_EDGES) atomicAdd(&g_cnt[dst[e]], 1);
}

__global__ void scan_kernel() {
    __shared__ int sh[1024];
    int t = threadIdx.x;
    const int per = (N_NODES + 1023) >> 10;  // 49
    int lo = t * per;
    int hi = lo + per; if (hi > N_NODES) hi = N_NODES;
    if (lo > N_NODES) lo = N_NODES;
    int sum = 0;
    for (int i = lo; i < hi; ++i) sum += g_cnt[i];
    sh[t] = sum;
    __syncthreads();
    for (int ofs = 1; ofs < 1024; ofs <<= 1) {
        int v = (t >= ofs) ? sh[t - ofs] : 0;
        __syncthreads();
        sh[t] += v;
        __syncthreads();
    }
    int run = (t == 0) ? 0 : sh[t - 1];
    for (int i = lo; i < hi; ++i) {
        g_roff[i] = run;
        g_cur[i]  = run;
        run += g_cnt[i];
    }
    if (t == 0) g_roff[N_NODES] = E_EDGES;
}

__global__ void scatter_kernel(const int* __restrict__ src, const int* __restrict__ dst) {
    int e = blockIdx.x * blockDim.x + threadIdx.x;
    if (e < E_EDGES) {
        int p = atomicAdd(&g_cur[dst[e]], 1);
        g_srcs[p] = src[e];
    }
}

// ---------------------------------------------------------------------------
// SGEMM 128x64x16, 256 threads, 8x4/thread, register-staged global prefetch.
// ---------------------------------------------------------------------------
__global__ __launch_bounds__(256) void sgemm_kernel(
    const float* __restrict__ A, const float* __restrict__ W,
    const float* __restrict__ bias, float* __restrict__ C,
    int M, int K, int Ncol)
{
    __shared__ float As[16][128 + 4];
    __shared__ float Bs[16][64];
    const int tid = threadIdx.x;
    const int br = blockIdx.x * 128;
    const int bc = blockIdx.y * 64;
    const int ty = tid >> 4;
    const int tx = tid & 15;

    float acc[8][4];
#pragma unroll
    for (int i = 0; i < 8; ++i)
#pragma unroll
        for (int j = 0; j < 4; ++j) acc[i][j] = 0.f;

    const int a_r0 = tid >> 2;           // 0..63
    const int a_c  = (tid & 3) << 2;     // 0,4,8,12
    const int b_r  = tid >> 4;           // 0..15
    const int b_c  = (tid & 15) << 2;    // 0..60

    const bool av0 = (br + a_r0) < M;
    const bool av1 = (br + a_r0 + 64) < M;
    const float* Ap0 = A + (size_t)(br + a_r0) * K + a_c;
    const float* Ap1 = A + (size_t)(br + a_r0 + 64) * K + a_c;
    const float* Wp  = W + (size_t)b_r * Ncol + bc + b_c;

    const float4 z4 = make_float4(0.f, 0.f, 0.f, 0.f);
    float4 va0 = av0 ? *(const float4*)Ap0 : z4;
    float4 va1 = av1 ? *(const float4*)Ap1 : z4;
    float4 vb  = *(const float4*)Wp;

    const int nT = K >> 4;
    for (int t = 0; t < nT; ++t) {
        As[a_c + 0][a_r0] = va0.x;
        As[a_c + 1][a_r0] = va0.y;
        As[a_c + 2][a_r0] = va0.z;
        As[a_c + 3][a_r0] = va0.w;
        As[a_c + 0][a_r0 + 64] = va1.x;
        As[a_c + 1][a_r0 + 64] = va1.y;
        As[a_c + 2][a_r0 + 64] = va1.z;
        As[a_c + 3][a_r0 + 64] = va1.w;
        *(float4*)&Bs[b_r][b_c] = vb;
        __syncthreads();

        if (t + 1 < nT) {  // issue next tile's global loads before computing
            va0 = av0 ? *(const float4*)(Ap0 + (t + 1) * 16) : z4;
            va1 = av1 ? *(const float4*)(Ap1 + (t + 1) * 16) : z4;
            vb  = *(const float4*)(Wp + (size_t)(t + 1) * 16 * Ncol);
        }
#pragma unroll
        for (int k = 0; k < 16; ++k) {
            float4 b4  = *(const float4*)&Bs[k][tx << 2];
            float4 alo = *(const float4*)&As[k][ty << 3];
            float4 ahi = *(const float4*)&As[k][(ty << 3) + 4];
            float av[8] = {alo.x, alo.y, alo.z, alo.w, ahi.x, ahi.y, ahi.z, ahi.w};
            float bv[4] = {b4.x, b4.y, b4.z, b4.w};
#pragma unroll
            for (int i = 0; i < 8; ++i)
#pragma unroll
                for (int j = 0; j < 4; ++j)
                    acc[i][j] = fmaf(av[i], bv[j], acc[i][j]);
        }
        __syncthreads();
    }

    float4 bb = *(const float4*)(bias + bc + (tx << 2));
    float bv[4] = {bb.x, bb.y, bb.z, bb.w};
#pragma unroll
    for (int i = 0; i < 8; ++i) {
        int gr = br + (ty << 3) + i;
        if (gr < M) {
            float4 o;
            o.x = acc[i][0] + bv[0];
            o.y = acc[i][1] + bv[1];
            o.z = acc[i][2] + bv[2];
            o.w = acc[i][3] + bv[3];
            *(float4*)(C + (size_t)gr * Ncol + bc + (tx << 2)) = o;
        }
    }
}

// ---------------------------------------------------------------------------
// Fused GAT edge kernels: PAIR-UNROLLED online softmax.
// Merged 2-edge update is exact:
//   nm = max(m, pA, pB); c=e^(m-nm); eA=e^(pA-nm); eB=e^(pB-nm)
//   s = s*c + eA + eB;  acc = acc*c + eA*rowA + eB*rowB
// ---------------------------------------------------------------------------
__device__ __forceinline__ float lrelu(float x) { return fmaxf(x, NEG_SLOPE * x); }
__device__ __forceinline__ float elu1(float x)  { return x > 0.f ? x : (__expf(x) - 1.f); }

__global__ __launch_bounds__(128) void gat_edge_h8(
    const float* __restrict__ h, const float* __restrict__ attnw,
    float* __restrict__ outp, int applyElu)
{
    int warp = (blockIdx.x * blockDim.x + threadIdx.x) >> 5;
    int lane = threadIdx.x & 31;
    if (warp >= N_NODES) return;
    const int n = warp;
    const float4* __restrict__ h4 = (const float4*)h;
    const float4* __restrict__ a4 = (const float4*)attnw;

    float4 a0 = a4[lane];
    float4 a1 = a4[32 + lane];
    float4 hd0 = h4[(size_t)n * 64 + lane];
    float4 hd1 = h4[(size_t)n * 64 + 32 + lane];

    float m0 = -CUDART_INF_F, m1 = -CUDART_INF_F;
    float s0 = 0.f, s1 = 0.f;
    float4 acc0 = make_float4(0.f, 0.f, 0.f, 0.f);
    float4 acc1 = make_float4(0.f, 0.f, 0.f, 0.f);

    const int beg = g_roff[n], end = g_roff[n + 1];
    int iA = g_srcs[beg];                           // degree >= 1 (self-edge)
    int iB = (beg + 1 < end) ? g_srcs[beg + 1] : iA;
    float4 A0 = h4[(size_t)iA * 64 + lane];
    float4 A1 = h4[(size_t)iA * 64 + 32 + lane];
    float4 B0 = h4[(size_t)iB * 64 + lane];
    float4 B1 = h4[(size_t)iB * 64 + 32 + lane];

    int j = beg;
    for (; j + 1 < end; j += 2) {
        // prefetch next pair (indices then rows); harmless dummies on last iter
        int jn = j + 2;
        int nAi = (jn < end) ? g_srcs[jn] : 0;
        int nBi = (jn + 1 < end) ? g_srcs[jn + 1] : nAi;
        float4 nA0 = h4[(size_t)nAi * 64 + lane];
        float4 nA1 = h4[(size_t)nAi * 64 + 32 + lane];
        float4 nB0 = h4[(size_t)nBi * 64 + lane];
        float4 nB1 = h4[(size_t)nBi * 64 + 32 + lane];

        // independent score chains for edge A and edge B
        float pA = lrelu(A0.x + hd0.x) * a0.x;
        pA = fmaf(lrelu(A0.y + hd0.y), a0.y, pA);
        pA = fmaf(lrelu(A0.z + hd0.z), a0.z, pA);
        pA = fmaf(lrelu(A0.w + hd0.w), a0.w, pA);
        float qA = lrelu(A1.x + hd1.x) * a1.x;
        qA = fmaf(lrelu(A1.y + hd1.y), a1.y, qA);
        qA = fmaf(lrelu(A1.z + hd1.z), a1.z, qA);
        qA = fmaf(lrelu(A1.w + hd1.w), a1.w, qA);
        float pB = lrelu(B0.x + hd0.x) * a0.x;
        pB = fmaf(lrelu(B0.y + hd0.y), a0.y, pB);
        pB = fmaf(lrelu(B0.z + hd0.z), a0.z, pB);
        pB = fmaf(lrelu(B0.w + hd0.w), a0.w, pB);
        float qB = lrelu(B1.x + hd1.x) * a1.x;
        qB = fmaf(lrelu(B1.y + hd1.y), a1.y, qB);
        qB = fmaf(lrelu(B1.z + hd1.z), a1.z, qB);
        qB = fmaf(lrelu(B1.w + hd1.w), a1.w, qB);

        // interleaved 8-lane butterflies (latency overlaps across 4 values)
        pA += __shfl_xor_sync(0xFFFFFFFFu, pA, 1);
        pB += __shfl_xor_sync(0xFFFFFFFFu, pB, 1);
        qA += __shfl_xor_sync(0xFFFFFFFFu, qA, 1);
        qB += __shfl_xor_sync(0xFFFFFFFFu, qB, 1);
        pA += __shfl_xor_sync(0xFFFFFFFFu, pA, 2);
        pB += __shfl_xor_sync(0xFFFFFFFFu, pB, 2);
        qA += __shfl_xor_sync(0xFFFFFFFFu, qA, 2);
        qB += __shfl_xor_sync(0xFFFFFFFFu, qB, 2);
        pA += __shfl_xor_sync(0xFFFFFFFFu, pA, 4);
        pB += __shfl_xor_sync(0xFFFFFFFFu, pB, 4);
        qA += __shfl_xor_sync(0xFFFFFFFFu, qA, 4);
        qB += __shfl_xor_sync(0xFFFFFFFFu, qB, 4);

        // merged online update, p-side (head lane>>3)
        {
            float nm = fmaxf(m0, fmaxf(pA, pB));
            float c  = __expf(m0 - nm);
            float eA = __expf(pA - nm);
            float eB = __expf(pB - nm);
            s0 = fmaf(s0, c, eA + eB); m0 = nm;
            acc0.x = fmaf(eB, B0.x, fmaf(eA, A0.x, acc0.x * c));
            acc0.y = fmaf(eB, B0.y, fmaf(eA, A0.y, acc0.y * c));
            acc0.z = fmaf(eB, B0.z, fmaf(eA, A0.z, acc0.z * c));
            acc0.w = fmaf(eB, B0.w, fmaf(eA, A0.w, acc0.w * c));
        }
        // merged online update, q-side (head 4+(lane>>3))
        {
            float nm = fmaxf(m1, fmaxf(qA, qB));
            float c  = __expf(m1 - nm);
            float eA = __expf(qA - nm);
            float eB = __expf(qB - nm);
            s1 = fmaf(s1, c, eA + eB); m1 = nm;
            acc1.x = fmaf(eB, B1.x, fmaf(eA, A1.x, acc1.x * c));
            acc1.y = fmaf(eB, B1.y, fmaf(eA, A1.y, acc1.y * c));
            acc1.z = fmaf(eB, B1.z, fmaf(eA, A1.z, acc1.z * c));
            acc1.w = fmaf(eB, B1.w, fmaf(eA, A1.w, acc1.w * c));
        }
        A0 = nA0; A1 = nA1; B0 = nB0; B1 = nB1;
    }

    if (j < end) {  // odd tail; its rows are already in A0/A1 (see prefetch trace)
        float p = lrelu(A0.x + hd0.x) * a0.x;
        p = fmaf(lrelu(A0.y + hd0.y), a0.y, p);
        p = fmaf(lrelu(A0.z + hd0.z), a0.z, p);
        p = fmaf(lrelu(A0.w + hd0.w), a0.w, p);
        float q = lrelu(A1.x + hd1.x) * a1.x;
        q = fmaf(lrelu(A1.y + hd1.y), a1.y, q);
        q = fmaf(lrelu(A1.z + hd1.z), a1.z, q);
        q = fmaf(lrelu(A1.w + hd1.w), a1.w, q);
        p += __shfl_xor_sync(0xFFFFFFFFu, p, 1);
        q += __shfl_xor_sync(0xFFFFFFFFu, q, 1);
        p += __shfl_xor_sync(0xFFFFFFFFu, p, 2);
        q += __shfl_xor_sync(0xFFFFFFFFu, q, 2);
        p += __shfl_xor_sync(0xFFFFFFFFu, p, 4);
        q += __shfl_xor_sync(0xFFFFFFFFu, q, 4);

        float nm = fmaxf(m0, p);
        float c  = __expf(m0 - nm);
        float e  = __expf(p - nm);
        s0 = fmaf(s0, c, e); m0 = nm;
        acc0.x = fmaf(e, A0.x, acc0.x * c);
        acc0.y = fmaf(e, A0.y, acc0.y * c);
        acc0.z = fmaf(e, A0.z, acc0.z * c);
        acc0.w = fmaf(e, A0.w, acc0.w * c);

        nm = fmaxf(m1, q);
        c  = __expf(m1 - nm);
        e  = __expf(q - nm);
        s1 = fmaf(s1, c, e); m1 = nm;
        acc1.x = fmaf(e, A1.x, acc1.x * c);
        acc1.y = fmaf(e, A1.y, acc1.y * c);
        acc1.z = fmaf(e, A1.z, acc1.z * c);
        acc1.w = fmaf(e, A1.w, acc1.w * c);
    }

    float inv0 = (s0 > 0.f) ? (1.f / s0) : 0.f;
    float inv1 = (s1 > 0.f) ? (1.f / s1) : 0.f;
    float4 o0 = make_float4(acc0.x * inv0, acc0.y * inv0, acc0.z * inv0, acc0.w * inv0);
    float4 o1 = make_float4(acc1.x * inv1, acc1.y * inv1, acc1.z * inv1, acc1.w * inv1);
    if (applyElu) {
        o0.x = elu1(o0.x); o0.y = elu1(o0.y); o0.z = elu1(o0.z); o0.w = elu1(o0.w);
        o1.x = elu1(o1.x); o1.y = elu1(o1.y); o1.z = elu1(o1.z); o1.w = elu1(o1.w);
    }
    float4* __restrict__ out4 = (float4*)outp;
    out4[(size_t)n * 64 + lane]      = o0;
    out4[(size_t)n * 64 + 32 + lane] = o1;
}

__global__ __launch_bounds__(256) void gat_edge_h1(
    const float* __restrict__ h, const float* __restrict__ attnw,
    float* __restrict__ outp)
{
    int warp = (blockIdx.x * blockDim.x + threadIdx.x) >> 5;
    int lane = threadIdx.x & 31;
    if (warp >= N_NODES) return;
    const int n = warp;
    const float2* __restrict__ h2 = (const float2*)h;
    float2 a  = ((const float2*)attnw)[lane];
    float2 hd = h2[(size_t)n * 32 + lane];

    float m = -CUDART_INF_F, ssum = 0.f;
    float2 acc = make_float2(0.f, 0.f);

    const int beg = g_roff[n], end = g_roff[n + 1];
    int iA = g_srcs[beg];
    int iB = (beg + 1 < end) ? g_srcs[beg + 1] : iA;
    float2 A = h2[(size_t)iA * 32 + lane];
    float2 B = h2[(size_t)iB * 32 + lane];

    int j = beg;
    for (; j + 1 < end; j += 2) {
        int jn = j + 2;
        int nAi = (jn < end) ? g_srcs[jn] : 0;
        int nBi = (jn + 1 < end) ? g_srcs[jn + 1] : nAi;
        float2 nA = h2[(size_t)nAi * 32 + lane];
        float2 nB = h2[(size_t)nBi * 32 + lane];

        float pA = lrelu(A.x + hd.x) * a.x;
        pA = fmaf(lrelu(A.y + hd.y), a.y, pA);
        float pB = lrelu(B.x + hd.x) * a.x;
        pB = fmaf(lrelu(B.y + hd.y), a.y, pB);
#pragma unroll
        for (int ofs = 1; ofs < 32; ofs <<= 1) {
            pA += __shfl_xor_sync(0xFFFFFFFFu, pA, ofs);
            pB += __shfl_xor_sync(0xFFFFFFFFu, pB, ofs);
        }

        float nm = fmaxf(m, fmaxf(pA, pB));
        float c  = __expf(m - nm);
        float eA = __expf(pA - nm);
        float eB = __expf(pB - nm);
        ssum = fmaf(ssum, c, eA + eB); m = nm;
        acc.x = fmaf(eB, B.x, fmaf(eA, A.x, acc.x * c));
        acc.y = fmaf(eB, B.y, fmaf(eA, A.y, acc.y * c));

        A = nA; B = nB;
    }
    if (j < end) {
        float p = lrelu(A.x + hd.x) * a.x;
        p = fmaf(lrelu(A.y + hd.y), a.y, p);
#pragma unroll
        for (int ofs = 1; ofs < 32; ofs <<= 1)
            p += __shfl_xor_sync(0xFFFFFFFFu, p, ofs);
        float nm = fmaxf(m, p);
        float c  = __expf(m - nm);
        float e  = __expf(p - nm);
        ssum = fmaf(ssum, c, e); m = nm;
        acc.x = fmaf(e, A.x, acc.x * c);
        acc.y = fmaf(e, A.y, acc.y * c);
    }
    float inv = (ssum > 0.f) ? (1.f / ssum) : 0.f;
    ((float2*)outp)[(size_t)n * 32 + lane] = make_float2(acc.x * inv, acc.y * inv);
}

// ---------------------------------------------------------------------------
// Coalesced max pool
// ---------------------------------------------------------------------------
__device__ __forceinline__ unsigned fmap(float f) {
    unsigned u = __float_as_uint(f);
    return (u & 0x80000000u) ? ~u : (u | 0x80000000u);
}

__global__ __launch_bounds__(256) void maxpool_kernel(const float* __restrict__ f) {
    __shared__ float4 sh[256];
    const float4* __restrict__ f4 = (const float4*)f;
    int cg = threadIdx.x & 15;
    int rr = threadIdx.x >> 4;
    float4 mx = make_float4(-CUDART_INF_F, -CUDART_INF_F, -CUDART_INF_F, -CUDART_INF_F);
    for (int n = blockIdx.x * 16 + rr; n < N_NODES; n += gridDim.x * 16) {
        float4 v = f4[(size_t)n * 16 + cg];
        mx.x = fmaxf(mx.x, v.x); mx.y = fmaxf(mx.y, v.y);
        mx.z = fmaxf(mx.z, v.z); mx.w = fmaxf(mx.w, v.w);
    }
    sh[threadIdx.x] = mx;
    __syncthreads();
    for (int ofs = 128; ofs >= 16; ofs >>= 1) {
        if (threadIdx.x < ofs) {
            float4 o = sh[threadIdx.x + ofs];
            float4 m2 = sh[threadIdx.x];
            m2.x = fmaxf(m2.x, o.x); m2.y = fmaxf(m2.y, o.y);
            m2.z = fmaxf(m2.z, o.z); m2.w = fmaxf(m2.w, o.w);
            sh[threadIdx.x] = m2;
        }
        __syncthreads();
    }
    if (threadIdx.x < 16) {
        float4 m2 = sh[threadIdx.x];
        atomicMax(&g_pool[threadIdx.x * 4 + 0], fmap(m2.x));
        atomicMax(&g_pool[threadIdx.x * 4 + 1], fmap(m2.y));
        atomicMax(&g_pool[threadIdx.x * 4 + 2], fmap(m2.z));
        atomicMax(&g_pool[threadIdx.x * 4 + 3], fmap(m2.w));
    }
}

__global__ void pool_final(float* __restrict__ out) {
    int c = threadIdx.x;
    if (c < 64) {
        unsigned v = g_pool[c];
        out[c] = (v & 0x80000000u) ? __uint_as_float(v ^ 0x80000000u)
                                   : __uint_as_float(~v);
    }
}

// ---------------------------------------------------------------------------
// Launch
// ---------------------------------------------------------------------------
extern "C" void kernel_launch(void* const* d_in, const int* in_sizes, int n_in,
                              void* d_out, int out_size)
{
    const float* x   = (const float*)d_in[0];
    const int*   src = (const int*)d_in[1];
    const int*   dst = (const int*)d_in[2];
    const float* W1  = (const float*)d_in[3];
    const float* b1  = (const float*)d_in[4];
    const float* at1 = (const float*)d_in[5];
    const float* W2  = (const float*)d_in[6];
    const float* b2  = (const float*)d_in[7];
    const float* at2 = (const float*)d_in[8];
    const float* W3  = (const float*)d_in[9];
    const float* b3  = (const float*)d_in[10];
    const float* at3 = (const float*)d_in[11];
    float* out = (float*)d_out;

    float *hP = nullptr, *fP = nullptr;
    int *cntP = nullptr;
    unsigned* poolP = nullptr;
    cudaGetSymbolAddress((void**)&hP, g_h);
    cudaGetSymbolAddress((void**)&fP, g_feat);
    cudaGetSymbolAddress((void**)&cntP, g_cnt);
    cudaGetSymbolAddress((void**)&poolP, g_pool);

    cudaMemsetAsync(cntP, 0, N_NODES * sizeof(int));
    cudaMemsetAsync(poolP, 0, 64 * sizeof(unsigned));
    hist_kernel<<<(E_EDGES + 255) / 256, 256>>>(dst);
    scan_kernel<<<1, 1024>>>();
    scatter_kernel<<<(E_EDGES + 255) / 256, 256>>>(src, dst);

    const int grid_h8 = N_NODES / 4;   // 4 warps/block @128 threads
    const int grid_h1 = N_NODES / 8;   // 8 warps/block @256 threads

    // Layer 1: x[50000,128] @ W1[128,256]
    {
        dim3 g((N_NODES + 127) / 128, 256 / 64);
        sgemm_kernel<<<g, 256>>>(x, W1, b1, hP, N_NODES, 128, 256);
        gat_edge_h8<<<grid_h8, 128>>>(hP, at1, fP, 1);
    }
    // Layer 2: feat[50000,256] @ W2[256,256]
    {
        dim3 g((N_NODES + 127) / 128, 256 / 64);
        sgemm_kernel<<<g, 256>>>(fP, W2, b2, hP, N_NODES, 256, 256);
        gat_edge_h8<<<grid_h8, 128>>>(hP, at2, fP, 1);
    }
    // Layer 3: feat[50000,256] @ W3[256,64]
    {
        dim3 g((N_NODES + 127) / 128, 1);
        sgemm_kernel<<<g, 256>>>(fP, W3, b3, hP, N_NODES, 256, 64);
        gat_edge_h1<<<grid_h1, 256>>>(hP, at3, fP);
    }
    maxpool_kernel<<<196, 256>>>(fP);
    pool_final<<<1, 64>>>(out);
}